// round 16
// baseline (speedup 1.0000x reference)
#include <cuda_runtime.h>
#include <cuda_fp16.h>
#include <cstdint>

// GINConv: out = SegmentSum_CSR(X[col]) @ W  ==  SegmentSum_CSR((X@W)[col])
// (N=100000, DEG=16, D=128). Column-split pipeline (halves h=0,1):
//   gemm_half(h): Y[:, 64h:64h+64] = X @ W[:, 64h:64h+64]   (fp16 MMA)
//   agg_half(h):  out[:, 64h:64h+64] = gather-sum of Y half rows
// Graph: gemm_a -> {agg_a || gemm_b} -> agg_b  (fork/join on 2nd stream)
// so agg's L2-bound gather overlaps gemm's HBM/tensor work.

#define MAX_NODES 100000
#define D 128

__device__ __half g_y[(size_t)MAX_NODES * D];  // 25.6 MB Y=X@W scratch (fp16)

#define SROWA 68  // A rows: 128 halves=64 words + 4 pad; 68%32=4 conflict-free
#define SROWB 36  // B rows:  64 halves=32 words + 4 pad; 36%32=4 conflict-free

__device__ __forceinline__ void mma_f16(float c[4], const unsigned a[4],
                                        const unsigned b[2]) {
    asm volatile(
        "mma.sync.aligned.m16n8k16.row.col.f32.f16.f16.f32 "
        "{%0,%1,%2,%3}, {%4,%5,%6,%7}, {%8,%9}, {%0,%1,%2,%3};"
        : "+f"(c[0]), "+f"(c[1]), "+f"(c[2]), "+f"(c[3])
        : "r"(a[0]), "r"(a[1]), "r"(a[2]), "r"(a[3]), "r"(b[0]), "r"(b[1]));
}

__device__ __forceinline__ void ldm_x4(unsigned& r0, unsigned& r1,
                                       unsigned& r2, unsigned& r3,
                                       uint32_t addr) {
    asm volatile(
        "ldmatrix.sync.aligned.m8n8.x4.shared.b16 {%0,%1,%2,%3}, [%4];"
        : "=r"(r0), "=r"(r1), "=r"(r2), "=r"(r3) : "r"(addr));
}

__device__ __forceinline__ void ldm_x4_trans(unsigned& r0, unsigned& r1,
                                             unsigned& r2, unsigned& r3,
                                             uint32_t addr) {
    asm volatile(
        "ldmatrix.sync.aligned.m8n8.x4.trans.shared.b16 {%0,%1,%2,%3}, [%4];"
        : "=r"(r0), "=r"(r1), "=r"(r2), "=r"(r3) : "r"(addr));
}

// ---------------------------------------------------------------------------
// gemm_half: Y[:, col_off:col_off+64] = X @ W[:, col_off:+64].
// CTA 256 threads, tile 128(M) x 64(N), K=128 one-shot.
// Warps 4(M) x 2(N) -> warp tile 32x32. smem 52KB.
// ---------------------------------------------------------------------------
__global__ void __launch_bounds__(256, 2)
gemm_half(const float* __restrict__ X, const float* __restrict__ W,
          int n_nodes, int col_off) {
    extern __shared__ unsigned smem32[];
    unsigned* As = smem32;                // [128][SROWA]
    unsigned* Bs = smem32 + 128 * SROWA;  // [128][SROWB]

    const int tid = threadIdx.x;
    const int lane = tid & 31;
    const int warp = tid >> 5;
    const int g = lane >> 2;
    const int t = lane & 3;

    const int block_row = blockIdx.x * 128;

    // --- fill As: X rows fp32 -> fp16 (full K=128) ---
    #pragma unroll
    for (int i = 0; i < 16; i++) {
        int idx = i * 256 + tid;
        int r = idx >> 5;
        int c4 = idx & 31;
        int gr = block_row + r;
        float4 v = make_float4(0.f, 0.f, 0.f, 0.f);
        if (gr < n_nodes) v = ((const float4*)X)[(size_t)gr * 32 + c4];
        __half2 h0 = __floats2half2_rn(v.x, v.y);
        __half2 h1 = __floats2half2_rn(v.z, v.w);
        uint2 u;
        u.x = *(unsigned*)&h0;
        u.y = *(unsigned*)&h1;
        *(uint2*)(As + r * SROWA + c4 * 2) = u;
    }
    // --- fill Bs: W[k][col_off..col_off+63] fp32 -> fp16 ---
    #pragma unroll
    for (int i = 0; i < 8; i++) {
        int idx = i * 256 + tid;   // 2048 float4 over 128 rows x 16
        int k = idx >> 4;
        int c4 = idx & 15;
        float4 v = ((const float4*)W)[k * 32 + (col_off >> 2) + c4];
        __half2 h0 = __floats2half2_rn(v.x, v.y);
        __half2 h1 = __floats2half2_rn(v.z, v.w);
        uint2 u;
        u.x = *(unsigned*)&h0;
        u.y = *(unsigned*)&h1;
        *(uint2*)(Bs + k * SROWB + c4 * 2) = u;
    }
    __syncthreads();

    const int warp_row = (warp & 3) * 32;   // 0,32,64,96
    const int warp_col = (warp >> 2) * 32;  // 0,32

    const int grp = lane >> 3;
    const int r8 = lane & 7;
    const int gL = grp & 1;
    const int gH = grp >> 1;

    const uint32_t as_base = (uint32_t)__cvta_generic_to_shared(As);
    const uint32_t bs_base = (uint32_t)__cvta_generic_to_shared(Bs);

    const uint32_t a_addr0 =
        as_base + ((warp_row + gL * 8 + r8) * SROWA + gH * 4) * 4;
    const uint32_t b_addr0 =
        bs_base + ((gL * 8 + r8) * SROWB) * 4 + (warp_col + gH * 8) * 2;

    float c[2][4][4];
    #pragma unroll
    for (int mi = 0; mi < 2; mi++)
        #pragma unroll
        for (int ni = 0; ni < 4; ni++)
            #pragma unroll
            for (int q = 0; q < 4; q++) c[mi][ni][q] = 0.f;

    #pragma unroll
    for (int ks = 0; ks < 8; ks++) {
        unsigned a[2][4];
        #pragma unroll
        for (int mi = 0; mi < 2; mi++) {
            uint32_t addr = a_addr0 + mi * (16 * SROWA * 4) + ks * 32;
            ldm_x4(a[mi][0], a[mi][1], a[mi][2], a[mi][3], addr);
        }
        unsigned b[4][2];
        #pragma unroll
        for (int nj = 0; nj < 2; nj++) {
            uint32_t addr = b_addr0 + ks * (16 * SROWB * 4) + nj * 32;
            ldm_x4_trans(b[2 * nj][0], b[2 * nj][1],
                         b[2 * nj + 1][0], b[2 * nj + 1][1], addr);
        }
        #pragma unroll
        for (int mi = 0; mi < 2; mi++)
            #pragma unroll
            for (int ni = 0; ni < 4; ni++)
                mma_f16(c[mi][ni], a[mi], b[ni]);
    }

    // --- epilogue: fp32 accum -> fp16 -> g_y half columns ---
    #pragma unroll
    for (int mi = 0; mi < 2; mi++) {
        int r_lo = block_row + warp_row + mi * 16 + g;
        int r_hi = r_lo + 8;
        #pragma unroll
        for (int ni = 0; ni < 4; ni++) {
            int col = col_off + warp_col + ni * 8 + 2 * t;
            if (r_lo < n_nodes) {
                __half2 h = __floats2half2_rn(c[mi][ni][0], c[mi][ni][1]);
                *(__half2*)(g_y + (size_t)r_lo * D + col) = h;
            }
            if (r_hi < n_nodes) {
                __half2 h = __floats2half2_rn(c[mi][ni][2], c[mi][ni][3]);
                *(__half2*)(g_y + (size_t)r_hi * D + col) = h;
            }
        }
    }
}

// ---------------------------------------------------------------------------
// agg_half: out[:, col_off:+64] = sum_e Y[col(e), col_off:+64].
// Warp per node; lane owns 1 uint (2 halves). 8-edge batch (MLP=8),
// depth-1 fp16 pair reduction, fp32 accumulate.
// ---------------------------------------------------------------------------
__global__ void __launch_bounds__(256, 8)
agg_half(const int* __restrict__ rowptr,
         const int* __restrict__ colidx,
         float* __restrict__ out, int n_nodes, int col_off) {
    int node = (int)((blockIdx.x * (unsigned)blockDim.x + threadIdx.x) >> 5);
    int lane = threadIdx.x & 31;
    if (node >= n_nodes) return;

    int s = rowptr[node];
    int e = rowptr[node + 1];

    const __half* __restrict__ Yb = g_y + col_off;
    float2 acc = make_float2(0.f, 0.f);

    int i = s;
    for (; i + 8 <= e; i += 8) {
        unsigned u[8];
        #pragma unroll
        for (int j = 0; j < 8; j++) {
            int c = colidx[i + j];
            u[j] = ((const unsigned*)(Yb + (size_t)c * D))[lane];
        }
        #pragma unroll
        for (int j = 0; j < 4; j++) {
            __half2 p = __hadd2(*(__half2*)&u[2 * j], *(__half2*)&u[2 * j + 1]);
            float2 f = __half22float2(p);
            acc.x += f.x;
            acc.y += f.y;
        }
    }
    for (; i < e; i++) {
        int c = colidx[i];
        unsigned u = ((const unsigned*)(Yb + (size_t)c * D))[lane];
        float2 f = __half22float2(*(__half2*)&u);
        acc.x += f.x;
        acc.y += f.y;
    }

    *(float2*)(out + (size_t)node * D + col_off + lane * 2) = acc;
}

// ---------------------------------------------------------------------------
// Stream/event resources created once at load time (before any capture).
// kernel_launch itself is deterministic and identical on every call.
// ---------------------------------------------------------------------------
static cudaStream_t g_s2 = nullptr;
static cudaEvent_t g_evFork = nullptr, g_evJoin = nullptr;
namespace {
struct StreamInit {
    StreamInit() {
        if (cudaStreamCreateWithFlags(&g_s2, cudaStreamNonBlocking) != cudaSuccess)
            g_s2 = nullptr;
        if (cudaEventCreateWithFlags(&g_evFork, cudaEventDisableTiming) != cudaSuccess)
            g_evFork = nullptr;
        if (cudaEventCreateWithFlags(&g_evJoin, cudaEventDisableTiming) != cudaSuccess)
            g_evJoin = nullptr;
    }
};
StreamInit g_stream_init;
}  // namespace

extern "C" void kernel_launch(void* const* d_in, const int* in_sizes, int n_in,
                              void* d_out, int out_size) {
    const float* X      = (const float*)d_in[0];
    const float* W      = (const float*)d_in[1];
    const int*   rowptr = (const int*)d_in[2];
    const int*   colidx = (const int*)d_in[3];
    float*       out    = (float*)d_out;

    int n_nodes = in_sizes[2] - 1;
    if (n_nodes > MAX_NODES) n_nodes = MAX_NODES;

    static const size_t smem_bytes =
        (size_t)(128 * SROWA + 128 * SROWB) * sizeof(unsigned);
    cudaFuncSetAttribute(gemm_half,
                         cudaFuncAttributeMaxDynamicSharedMemorySize,
                         (int)smem_bytes);
    int gemm_blocks = (n_nodes + 127) / 128;
    int agg_blocks = (n_nodes + 7) / 8;

    if (g_s2 && g_evFork && g_evJoin) {
        // chain A (default stream): gemm_a -> agg_a
        gemm_half<<<gemm_blocks, 256, smem_bytes>>>(X, W, n_nodes, 0);
        cudaEventRecord(g_evFork, 0);
        agg_half<<<agg_blocks, 256>>>(rowptr, colidx, out, n_nodes, 0);
        // chain B (s2): gemm_b (after gemm_a) -> agg_b; overlaps agg_a
        cudaStreamWaitEvent(g_s2, g_evFork, 0);
        gemm_half<<<gemm_blocks, 256, smem_bytes, g_s2>>>(X, W, n_nodes, 64);
        agg_half<<<agg_blocks, 256, 0, g_s2>>>(rowptr, colidx, out, n_nodes, 64);
        cudaEventRecord(g_evJoin, g_s2);
        cudaStreamWaitEvent(0, g_evJoin, 0);
    } else {
        // fallback: sequential on default stream
        gemm_half<<<gemm_blocks, 256, smem_bytes>>>(X, W, n_nodes, 0);
        gemm_half<<<gemm_blocks, 256, smem_bytes>>>(X, W, n_nodes, 64);
        agg_half<<<agg_blocks, 256>>>(rowptr, colidx, out, n_nodes, 0);
        agg_half<<<agg_blocks, 256>>>(rowptr, colidx, out, n_nodes, 64);
    }
}

// round 17
// speedup vs baseline: 1.4703x; 1.4703x over previous
#include <cuda_runtime.h>
#include <cuda_fp16.h>
#include <cstdint>

// GINConv: out = SegmentSum_CSR(X[col]) @ W  ==  SegmentSum_CSR((X@W)[col])
// (N=100000, DEG=16, D=128). Two kernels:
//   K1: GEMM Y = X @ W, software-pipelined: CTA = 256 rows as 4 chunks of 64,
//       double-buffered A in smem, next chunk's X prefetched into registers
//       during current chunk's MMA+epilogue. B filled once. 2 CTAs/SM.
//   K2: gather-aggregate Y rows (R9: 8-edge batch MLP=8, depth-1 fp16 pair
//       reduction, fp32 accumulate, 32 regs). At the chip LTS cap.

#define MAX_NODES 100000
#define D 128

__device__ __half g_y[(size_t)MAX_NODES * D];  // 25.6 MB Y=X@W scratch (fp16)

// smem row stride: 136 halves = 68 words; 68 mod 32 = 4 -> ldmatrix rows hit
// banks 4r..4r+3, disjoint over 8 rows per phase. Conflict-free.
#define SROW32 68

__device__ __forceinline__ void mma_f16(float c[4], const unsigned a[4],
                                        const unsigned b[2]) {
    asm volatile(
        "mma.sync.aligned.m16n8k16.row.col.f32.f16.f16.f32 "
        "{%0,%1,%2,%3}, {%4,%5,%6,%7}, {%8,%9}, {%0,%1,%2,%3};"
        : "+f"(c[0]), "+f"(c[1]), "+f"(c[2]), "+f"(c[3])
        : "r"(a[0]), "r"(a[1]), "r"(a[2]), "r"(a[3]), "r"(b[0]), "r"(b[1]));
}

__device__ __forceinline__ void ldm_x4(unsigned& r0, unsigned& r1,
                                       unsigned& r2, unsigned& r3,
                                       uint32_t addr) {
    asm volatile(
        "ldmatrix.sync.aligned.m8n8.x4.shared.b16 {%0,%1,%2,%3}, [%4];"
        : "=r"(r0), "=r"(r1), "=r"(r2), "=r"(r3) : "r"(addr));
}

__device__ __forceinline__ void ldm_x4_trans(unsigned& r0, unsigned& r1,
                                             unsigned& r2, unsigned& r3,
                                             uint32_t addr) {
    asm volatile(
        "ldmatrix.sync.aligned.m8n8.x4.trans.shared.b16 {%0,%1,%2,%3}, [%4];"
        : "=r"(r0), "=r"(r1), "=r"(r2), "=r"(r3) : "r"(addr));
}

// ---------------------------------------------------------------------------
// K1: Y = X @ W, pipelined. CTA 256 threads, 4 chunks of 64(M) x 128(N),
// K=128. Warps 2(M) x 4(N) per chunk -> warp tile 32x32.
// ---------------------------------------------------------------------------
__global__ void __launch_bounds__(256, 2)
gemm_kernel(const float* __restrict__ X, const float* __restrict__ W,
            int n_nodes) {
    extern __shared__ unsigned smem32[];
    unsigned* Bs = smem32;                          // [128][SROW32]
    unsigned* Ab[2] = {smem32 + 128 * SROW32,       // [64][SROW32]
                       smem32 + (128 + 64) * SROW32};

    const int tid = threadIdx.x;
    const int lane = tid & 31;
    const int warp = tid >> 5;
    const int g = lane >> 2;
    const int t = lane & 3;

    const int cta_row = blockIdx.x * 256;

    // thread's slot within a 64-row chunk: 8 float4 (rows 0..63 x 32 cols4)
    // idx = i*256 + tid ; r = idx>>5 ; c4 = idx&31

    // --- fill Bs once: W [k][n] fp32 -> fp16 ---
    #pragma unroll
    for (int i = 0; i < 16; i++) {
        int idx = i * 256 + tid;
        int k = idx >> 5;
        int c4 = idx & 31;
        float4 v = ((const float4*)W)[idx];
        __half2 h0 = __floats2half2_rn(v.x, v.y);
        __half2 h1 = __floats2half2_rn(v.z, v.w);
        uint2 u;
        u.x = *(unsigned*)&h0;
        u.y = *(unsigned*)&h1;
        *(uint2*)(Bs + k * SROW32 + c4 * 2) = u;
    }

    // --- prologue: load chunk 0 -> regs, convert -> Ab[0] ---
    float4 pf[8];
    #pragma unroll
    for (int i = 0; i < 8; i++) {
        int idx = i * 256 + tid;
        int r = idx >> 5;
        int c4 = idx & 31;
        int gr = cta_row + r;
        pf[i] = (gr < n_nodes) ? ((const float4*)X)[(size_t)gr * 32 + c4]
                               : make_float4(0.f, 0.f, 0.f, 0.f);
    }
    #pragma unroll
    for (int i = 0; i < 8; i++) {
        int idx = i * 256 + tid;
        int r = idx >> 5;
        int c4 = idx & 31;
        __half2 h0 = __floats2half2_rn(pf[i].x, pf[i].y);
        __half2 h1 = __floats2half2_rn(pf[i].z, pf[i].w);
        uint2 u;
        u.x = *(unsigned*)&h0;
        u.y = *(unsigned*)&h1;
        *(uint2*)(Ab[0] + r * SROW32 + c4 * 2) = u;
    }
    __syncthreads();

    const int warp_row = (warp & 1) * 32;   // 0,32 within chunk
    const int warp_col = (warp >> 1) * 32;  // 0,32,64,96

    const int grp = lane >> 3;
    const int r8 = lane & 7;
    const int gL = grp & 1;
    const int gH = grp >> 1;

    const uint32_t bs_base = (uint32_t)__cvta_generic_to_shared(Bs);
    const uint32_t ab_base[2] = {
        (uint32_t)__cvta_generic_to_shared(Ab[0]),
        (uint32_t)__cvta_generic_to_shared(Ab[1])};

    const uint32_t b_addr0 =
        bs_base + ((gL * 8 + r8) * SROW32) * 4 + (warp_col + gH * 8) * 2;
    const uint32_t a_off =
        ((warp_row + gL * 8 + r8) * SROW32 + gH * 4) * 4;

    for (int c = 0; c < 4; c++) {
        const int chunk_row = cta_row + c * 64;
        if (chunk_row >= n_nodes) break;

        // 1) prefetch next chunk's X into regs (independent of MMA below)
        if (c + 1 < 4) {
            #pragma unroll
            for (int i = 0; i < 8; i++) {
                int idx = i * 256 + tid;
                int r = idx >> 5;
                int c4 = idx & 31;
                int gr = chunk_row + 64 + r;
                pf[i] = (gr < n_nodes)
                            ? ((const float4*)X)[(size_t)gr * 32 + c4]
                            : make_float4(0.f, 0.f, 0.f, 0.f);
            }
        }

        // 2) MMA chunk c from Ab[c&1]
        const uint32_t a_addr0 = ab_base[c & 1] + a_off;
        float acc[2][4][4];
        #pragma unroll
        for (int mi = 0; mi < 2; mi++)
            #pragma unroll
            for (int ni = 0; ni < 4; ni++)
                #pragma unroll
                for (int q = 0; q < 4; q++) acc[mi][ni][q] = 0.f;

        #pragma unroll
        for (int ks = 0; ks < 8; ks++) {
            unsigned a[2][4];
            #pragma unroll
            for (int mi = 0; mi < 2; mi++) {
                uint32_t addr = a_addr0 + mi * (16 * SROW32 * 4) + ks * 32;
                ldm_x4(a[mi][0], a[mi][1], a[mi][2], a[mi][3], addr);
            }
            unsigned b[4][2];
            #pragma unroll
            for (int nj = 0; nj < 2; nj++) {
                uint32_t addr = b_addr0 + ks * (16 * SROW32 * 4) + nj * 32;
                ldm_x4_trans(b[2 * nj][0], b[2 * nj][1],
                             b[2 * nj + 1][0], b[2 * nj + 1][1], addr);
            }
            #pragma unroll
            for (int mi = 0; mi < 2; mi++)
                #pragma unroll
                for (int ni = 0; ni < 4; ni++)
                    mma_f16(acc[mi][ni], a[mi], b[ni]);
        }

        // 3) epilogue chunk c
        #pragma unroll
        for (int mi = 0; mi < 2; mi++) {
            int r_lo = chunk_row + warp_row + mi * 16 + g;
            int r_hi = r_lo + 8;
            #pragma unroll
            for (int ni = 0; ni < 4; ni++) {
                int col = warp_col + ni * 8 + 2 * t;
                if (r_lo < n_nodes) {
                    __half2 h = __floats2half2_rn(acc[mi][ni][0], acc[mi][ni][1]);
                    *(__half2*)(g_y + (size_t)r_lo * D + col) = h;
                }
                if (r_hi < n_nodes) {
                    __half2 h = __floats2half2_rn(acc[mi][ni][2], acc[mi][ni][3]);
                    *(__half2*)(g_y + (size_t)r_hi * D + col) = h;
                }
            }
        }

        // 4) convert prefetched regs -> other A buffer (read by MMA c+1)
        if (c + 1 < 4) {
            unsigned* dst = Ab[(c + 1) & 1];
            #pragma unroll
            for (int i = 0; i < 8; i++) {
                int idx = i * 256 + tid;
                int r = idx >> 5;
                int c4 = idx & 31;
                __half2 h0 = __floats2half2_rn(pf[i].x, pf[i].y);
                __half2 h1 = __floats2half2_rn(pf[i].z, pf[i].w);
                uint2 u;
                u.x = *(unsigned*)&h0;
                u.y = *(unsigned*)&h1;
                *(uint2*)(dst + r * SROW32 + c4 * 2) = u;
            }
            __syncthreads();
        }
    }
}

// ---------------------------------------------------------------------------
// K2: aggregation (R9 proven version). Warp per node, lane owns 4 dims.
// 8-edge load batch (MLP=8), depth-1 fp16 pair reduction, fp32 accumulate.
// ---------------------------------------------------------------------------
__global__ void __launch_bounds__(256, 8)
agg_kernel(const int* __restrict__ rowptr,
           const int* __restrict__ colidx,
           float* __restrict__ out, int n_nodes) {
    int node = (int)((blockIdx.x * (unsigned)blockDim.x + threadIdx.x) >> 5);
    int lane = threadIdx.x & 31;
    if (node >= n_nodes) return;

    int s = rowptr[node];
    int e = rowptr[node + 1];

    const __half* __restrict__ Y = g_y;
    float4 acc = make_float4(0.f, 0.f, 0.f, 0.f);

    int i = s;
    for (; i + 8 <= e; i += 8) {
        uint2 u[8];
        #pragma unroll
        for (int j = 0; j < 8; j++) {
            int c = colidx[i + j];
            u[j] = ((const uint2*)(Y + (size_t)c * D))[lane];
        }
        #pragma unroll
        for (int j = 0; j < 4; j++) {
            __half2 lo = __hadd2(*(__half2*)&u[2 * j].x, *(__half2*)&u[2 * j + 1].x);
            __half2 hi = __hadd2(*(__half2*)&u[2 * j].y, *(__half2*)&u[2 * j + 1].y);
            float2 a = __half22float2(lo);
            float2 b = __half22float2(hi);
            acc.x += a.x; acc.y += a.y; acc.z += b.x; acc.w += b.y;
        }
    }
    for (; i < e; i++) {
        int c = colidx[i];
        uint2 u = ((const uint2*)(Y + (size_t)c * D))[lane];
        float2 a = __half22float2(*(__half2*)&u.x);
        float2 b = __half22float2(*(__half2*)&u.y);
        acc.x += a.x; acc.y += a.y; acc.z += b.x; acc.w += b.y;
    }

    ((float4*)out)[(size_t)node * 32 + lane] = acc;
}

// ---------------------------------------------------------------------------
extern "C" void kernel_launch(void* const* d_in, const int* in_sizes, int n_in,
                              void* d_out, int out_size) {
    const float* X      = (const float*)d_in[0];
    const float* W      = (const float*)d_in[1];
    const int*   rowptr = (const int*)d_in[2];
    const int*   colidx = (const int*)d_in[3];
    float*       out    = (float*)d_out;

    int n_nodes = in_sizes[2] - 1;
    if (n_nodes > MAX_NODES) n_nodes = MAX_NODES;

    // K1: Y = X @ W, pipelined, 256 rows per CTA. smem 69.6KB -> 2 CTAs/SM
    static const size_t smem_bytes =
        (size_t)((128 + 2 * 64) * SROW32) * sizeof(unsigned);
    cudaFuncSetAttribute(gemm_kernel,
                         cudaFuncAttributeMaxDynamicSharedMemorySize,
                         (int)smem_bytes);
    int gemm_blocks = (n_nodes + 255) / 256;
    gemm_kernel<<<gemm_blocks, 256, smem_bytes>>>(X, W, n_nodes);

    // K2: out[r] = sum_e Y[col(e)]  (warp per node)
    int agg_blocks = (n_nodes + 7) / 8;
    agg_kernel<<<agg_blocks, 256>>>(rowptr, colidx, out, n_nodes);
}